// round 15
// baseline (speedup 1.0000x reference)
#include <cuda_runtime.h>
#include <cuda_bf16.h>
#include <cstdint>

#define NUM_CLASSES 100000
#define EMBED 512
#define BATCH_N 4096
#define LAMBDA_C 0.01f
#define ALPHA_C 0.1f

#define NCS ((size_t)NUM_CLASSES * EMBED)   // 51,200,000 floats
#define GRID (NUM_CLASSES / 2)               // 50,000 blocks, 2 rows each
#define BUILD_BLOCKS 16

// Zero-initialized at load. g_head zeros restored by head blocks each call;
// g_done reset by a memset graph node before each kernel run.
// g_head[c]: 0 = untouched, i+1 = sample i heads class c's chain.
__device__ int g_head[NUM_CLASSES];
__device__ int g_next[BATCH_N];
__device__ unsigned g_done;

__global__ __launch_bounds__(256)
void fused_kernel(const int* __restrict__ y,
                  const float4* __restrict__ centers4,
                  const float4* __restrict__ batch4,
                  float* __restrict__ dst,       // new_centers (= out+1)
                  float* __restrict__ loss) {
    const int bid = blockIdx.x;
    const int tid = threadIdx.x;

    // ---- build (blocks 0-15: wave-1 residents, so gate cannot deadlock) ----
    if (bid < BUILD_BLOCKS) {
        if (bid == 0 && tid == 0) *loss = 0.0f;   // before gate opens
        const int i = bid * 256 + tid;            // 16*256 = 4096 samples
        const int c = y[i];
        const int old = atomicExch(&g_head[c], i + 1);
        g_next[i] = old;
        __threadfence();                          // release chains + loss zero
        __syncthreads();
        if (tid == 0) atomicAdd(&g_done, 1u);
    }

    // ---- unconditional streaming copy (independent of g_head) ----
    const int row = bid * 2 + (tid >> 7);
    const int t   = tid & 127;                    // float4 index within row
    float4 c4 = __ldcs(centers4 + (size_t)row * (EMBED / 4) + t);
    float* d = dst + (size_t)row * EMBED + t * 4; // dst misaligned by 4B
    __stcs(d + 0, c4.x);
    __stcs(d + 1, c4.y);
    __stcs(d + 2, c4.z);
    __stcs(d + 3, c4.w);

    // ---- gate: wait for chain build (opens ~first-wave; spin is rare) ----
    if (tid == 0) {
        while (*(volatile unsigned*)&g_done < (unsigned)BUILD_BLOCKS)
            __nanosleep(64);
        __threadfence();                          // acquire chain writes
    }
    __syncthreads();  // also orders copy stores before rare-path overwrite

    // ---- rare path: touched row -> overwrite with update + loss ----
    const int h = __ldcg(&g_head[row]);           // half-block uniform
    if (h > 0) {
        float ax = 0.f, ay = 0.f, az = 0.f, aw = 0.f, ls = 0.f;
        int s = h;
        while (s > 0) {
            float4 b4 = batch4[(size_t)(s - 1) * (EMBED / 4) + t];
            float dx = b4.x - c4.x;
            float dy = b4.y - c4.y;
            float dz = b4.z - c4.z;
            float dw = b4.w - c4.w;
            ax += dx; ay += dy; az += dz; aw += dw;
            ls += dx * dx + dy * dy + dz * dz + dw * dw;
            s = g_next[s - 1];
        }
        // same-thread same-address: ordered after the copy stores
        d[0] = c4.x + ALPHA_C * ax;
        d[1] = c4.y + ALPHA_C * ay;
        d[2] = c4.z + ALPHA_C * az;
        d[3] = c4.w + ALPHA_C * aw;

        #pragma unroll
        for (int off = 16; off > 0; off >>= 1)
            ls += __shfl_xor_sync(0xFFFFFFFFu, ls, off);
        if ((t & 31) == 0)
            atomicAdd(loss, ls * (LAMBDA_C / (float)BATCH_N));

        if (t == 0) g_head[row] = 0;              // restore zero-invariant
    }
}

extern "C" void kernel_launch(void* const* d_in, const int* in_sizes, int n_in,
                              void* d_out, int out_size) {
    const int*   y       = (const int*)d_in[0];
    const float* batch   = (const float*)d_in[1];
    const float* centers = (const float*)d_in[2];

    float* out = (float*)d_out;

    float* loss_ptr;
    float* new_centers;
    if (out_size == (int)(NCS + 1)) {
        loss_ptr = out;
        new_centers = out + 1;
    } else {
        new_centers = out;
        loss_ptr = out + NCS;
    }

    // reset the build-done counter (graph memset node, ~1us)
    void* done_ptr = nullptr;
    cudaGetSymbolAddress(&done_ptr, g_done);
    cudaMemsetAsync(done_ptr, 0, sizeof(unsigned), 0);

    fused_kernel<<<GRID, 256>>>(y,
        reinterpret_cast<const float4*>(centers),
        reinterpret_cast<const float4*>(batch),
        new_centers, loss_ptr);
}

// round 16
// speedup vs baseline: 1.4858x; 1.4858x over previous
#include <cuda_runtime.h>
#include <cuda_bf16.h>
#include <cstdint>

#define NUM_CLASSES 100000
#define EMBED 512
#define BATCH_N 4096
#define LAMBDA_C 0.01f
#define ALPHA_C 0.1f

#define NCS ((size_t)NUM_CLASSES * EMBED)   // 51,200,000 floats
#define GRID (NUM_CLASSES / 4)               // 25,000 blocks, 4 rows each

// Zero-initialized at load; head blocks restore zeros each call, so the
// invariant holds across graph replays. g_head[c]: 0=untouched, i+1=head.
__device__ int g_head[NUM_CLASSES];
__device__ int g_next[BATCH_N];

// 1) build chains + zero loss slot (proven 4.8us)
__global__ __launch_bounds__(256)
void build_kernel(const int* __restrict__ y, float* __restrict__ loss) {
    int i = blockIdx.x * blockDim.x + threadIdx.x;
    if (i == 0) *loss = 0.0f;
    if (i < BATCH_N) {
        int c = y[i];
        int old = atomicExch(&g_head[c], i + 1);
        g_next[i] = old;
    }
}

// Helper: walk class chain and overwrite row r in dst. c4 = this thread's
// center float4 for row r; d = its 4 dst scalars.
__device__ __forceinline__ void apply_row(int h, int r, int t,
                                          float4 c4,
                                          const float4* __restrict__ batch4,
                                          float* __restrict__ d,
                                          float* __restrict__ loss) {
    float ax = 0.f, ay = 0.f, az = 0.f, aw = 0.f, ls = 0.f;
    int s = h;
    while (s > 0) {
        float4 b4 = batch4[(size_t)(s - 1) * (EMBED / 4) + t];
        float dx = b4.x - c4.x;
        float dy = b4.y - c4.y;
        float dz = b4.z - c4.z;
        float dw = b4.w - c4.w;
        ax += dx; ay += dy; az += dz; aw += dw;
        ls += dx * dx + dy * dy + dz * dz + dw * dw;
        s = g_next[s - 1];
    }
    d[0] = c4.x + ALPHA_C * ax;
    d[1] = c4.y + ALPHA_C * ay;
    d[2] = c4.z + ALPHA_C * az;
    d[3] = c4.w + ALPHA_C * aw;

    #pragma unroll
    for (int off = 16; off > 0; off >>= 1)
        ls += __shfl_xor_sync(0xFFFFFFFFu, ls, off);
    if ((t & 31) == 0)
        atomicAdd(loss, ls * (LAMBDA_C / (float)BATCH_N));

    if (t == 0) g_head[r] = 0;              // restore zero-invariant
}

// 2) fused streaming pass, ILP=2: block handles 4 rows; each thread copies
//    one float4 from each of TWO rows (independent loads). g_head loads are
//    issued first; rare path runs after both copy stores.
__global__ __launch_bounds__(256)
void fused_copy_apply_kernel(const float4* __restrict__ centers4,
                             const float4* __restrict__ batch4,
                             float* __restrict__ dst,
                             float* __restrict__ loss) {
    const int bid = blockIdx.x;
    const int tid = threadIdx.x;
    const int t   = tid & 127;               // float4 index within a row
    const int rA  = bid * 4 + (tid >> 7);    // rows rA and rA+2
    const int rB  = rA + 2;

    // issue head loads first (resolved well before the branches)
    const int hA = g_head[rA];
    const int hB = g_head[rB];

    // two independent copy loads
    const size_t cb = (size_t)bid * 512;     // block's first float4 chunk
    float4 A = __ldcs(centers4 + cb + tid);          // row rA
    float4 B = __ldcs(centers4 + cb + 256 + tid);    // row rB

    // copy stores (dst = out+1, misaligned -> scalars)
    float* dA = dst + (size_t)rA * EMBED + t * 4;
    __stcs(dA + 0, A.x);
    __stcs(dA + 1, A.y);
    __stcs(dA + 2, A.z);
    __stcs(dA + 3, A.w);
    float* dB = dst + (size_t)rB * EMBED + t * 4;
    __stcs(dB + 0, B.x);
    __stcs(dB + 1, B.y);
    __stcs(dB + 2, B.z);
    __stcs(dB + 3, B.w);

    // rare overwrites (same-thread same-address: ordered after copy stores)
    if (hA > 0) apply_row(hA, rA, t, A, batch4, dA, loss);
    if (hB > 0) apply_row(hB, rB, t, B, batch4, dB, loss);
}

extern "C" void kernel_launch(void* const* d_in, const int* in_sizes, int n_in,
                              void* d_out, int out_size) {
    const int*   y       = (const int*)d_in[0];
    const float* batch   = (const float*)d_in[1];
    const float* centers = (const float*)d_in[2];

    float* out = (float*)d_out;

    float* loss_ptr;
    float* new_centers;
    if (out_size == (int)(NCS + 1)) {
        loss_ptr = out;
        new_centers = out + 1;
    } else {
        new_centers = out;
        loss_ptr = out + NCS;
    }

    // 1) chains + loss zero
    build_kernel<<<(BATCH_N + 255) / 256, 256>>>(y, loss_ptr);

    // 2) fused streaming copy (ILP=2) + sparse overwrite
    fused_copy_apply_kernel<<<GRID, 256>>>(
        reinterpret_cast<const float4*>(centers),
        reinterpret_cast<const float4*>(batch),
        new_centers, loss_ptr);
}